// round 1
// baseline (speedup 1.0000x reference)
#include <cuda_runtime.h>
#include <cuda_bf16.h>
#include <cstdint>

// Problem constants
#define B_    64
#define T_    512
#define F_    1024
#define H_    52
#define START_ 50
#define STOP_  51
#define BT_   (B_ * T_)

// Scratch (static device globals; no runtime allocation)
__device__ float g_emit[BT_ * H_];   // raw emit scores [b*T+t][h]
__device__ float g_diff[B_];         // fwd - gold per batch

// ---------- packed fp32x2 helpers ----------
__device__ __forceinline__ unsigned long long pk2(float lo, float hi) {
    unsigned long long d;
    asm("mov.b64 %0, {%1, %2};" : "=l"(d) : "r"(__float_as_uint(lo)), "r"(__float_as_uint(hi)));
    return d;
}
__device__ __forceinline__ void upk2(unsigned long long v, float& lo, float& hi) {
    unsigned int a, b;
    asm("mov.b64 {%0, %1}, %2;" : "=r"(a), "=r"(b) : "l"(v));
    lo = __uint_as_float(a); hi = __uint_as_float(b);
}
__device__ __forceinline__ unsigned long long fma2(unsigned long long a, unsigned long long b,
                                                   unsigned long long c) {
    unsigned long long d;
    asm("fma.rn.f32x2 %0, %1, %2, %3;" : "=l"(d) : "l"(a), "l"(b), "l"(c));
    return d;
}
__device__ __forceinline__ unsigned long long add2(unsigned long long a, unsigned long long b) {
    unsigned long long d;
    asm("add.rn.f32x2 %0, %1, %2;" : "=l"(d) : "l"(a), "l"(b));
    return d;
}

// ============================================================
// Kernel 1: emit = features @ W^T + b   (M=32768, N=52, K=1024)
// 128 blocks x 256 threads. Block tile: 256 rows x 56 cols (52 used).
// Thread: 4 rows (rt, rt+64, rt+128, rt+192) x 7 col-pairs (f32x2).
// ============================================================
__global__ void __launch_bounds__(256, 1)
emit_gemm_kernel(const float* __restrict__ feat, const float* __restrict__ W,
                 const float* __restrict__ bias) {
    __shared__ float sF[32 * 257];  // [kk][row], stride 257 (conflict-free)
    __shared__ float sW[32 * 58];   // [kk][h],   stride 58, h in [0,56)

    const int tid = threadIdx.x;
    const int cg = tid >> 6;       // 0..3  (column group: 14 cols each)
    const int rt = tid & 63;       // 0..63 (row thread)
    const int blockRow = blockIdx.x * 256;

    const int lrow = tid >> 3;     // load phase: 0..31
    const int ljj  = tid & 7;      // 0..7 (float4 along k)
    const int wkk  = tid & 31;
    const int whb  = tid >> 5;     // 0..7

    unsigned long long acc[4][7];
#pragma unroll
    for (int r = 0; r < 4; r++)
#pragma unroll
        for (int j = 0; j < 7; j++) acc[r][j] = 0ULL;

    float4 fv[8];
    float  wv[7];

    auto load_chunk = [&](int k0) {
#pragma unroll
        for (int it = 0; it < 8; it++) {
            int row = lrow + it * 32;
            fv[it] = *reinterpret_cast<const float4*>(
                &feat[(size_t)(blockRow + row) * F_ + k0 + ljj * 4]);
        }
#pragma unroll
        for (int it = 0; it < 7; it++) {
            int hh = whb + it * 8;  // 0..55
            wv[it] = (hh < H_) ? W[(size_t)hh * F_ + k0 + wkk] : 0.0f;
        }
    };
    auto store_chunk = [&]() {
#pragma unroll
        for (int it = 0; it < 8; it++) {
            int row = lrow + it * 32;
            sF[(ljj * 4 + 0) * 257 + row] = fv[it].x;
            sF[(ljj * 4 + 1) * 257 + row] = fv[it].y;
            sF[(ljj * 4 + 2) * 257 + row] = fv[it].z;
            sF[(ljj * 4 + 3) * 257 + row] = fv[it].w;
        }
#pragma unroll
        for (int it = 0; it < 7; it++) sW[wkk * 58 + whb + it * 8] = wv[it];
    };

    load_chunk(0);
    for (int k0 = 0; k0 < F_; k0 += 32) {
        __syncthreads();   // previous compute done
        store_chunk();
        __syncthreads();   // smem ready
        if (k0 + 32 < F_) load_chunk(k0 + 32);  // prefetch next (overlaps compute)

#pragma unroll 4
        for (int kk = 0; kk < 32; kk++) {
            float f0 = sF[kk * 257 + rt];
            float f1 = sF[kk * 257 + rt + 64];
            float f2 = sF[kk * 257 + rt + 128];
            float f3 = sF[kk * 257 + rt + 192];
            unsigned long long p0 = pk2(f0, f0);
            unsigned long long p1 = pk2(f1, f1);
            unsigned long long p2 = pk2(f2, f2);
            unsigned long long p3 = pk2(f3, f3);
#pragma unroll
            for (int j = 0; j < 7; j++) {
                unsigned long long w2 = *reinterpret_cast<const unsigned long long*>(
                    &sW[kk * 58 + cg * 14 + 2 * j]);
                acc[0][j] = fma2(p0, w2, acc[0][j]);
                acc[1][j] = fma2(p1, w2, acc[1][j]);
                acc[2][j] = fma2(p2, w2, acc[2][j]);
                acc[3][j] = fma2(p3, w2, acc[3][j]);
            }
        }
    }

    // epilogue: + bias, store valid col pairs (< 52)
#pragma unroll
    for (int r = 0; r < 4; r++) {
        int row = blockRow + rt + r * 64;
#pragma unroll
        for (int j = 0; j < 7; j++) {
            int col = cg * 14 + 2 * j;
            if (col + 1 < H_) {
                float lo, hi;
                upk2(acc[r][j], lo, hi);
                lo += __ldg(&bias[col]);
                hi += __ldg(&bias[col + 1]);
                float2 o = make_float2(lo, hi);
                *reinterpret_cast<float2*>(&g_emit[(size_t)row * H_ + col]) = o;
            }
        }
    }
}

// ============================================================
// Kernel 2: per-batch CRF forward (prob-space scan) + gold score
// 64 blocks x 64 threads. Thread h<52 owns destination state h.
// p_{t+1}[h'] = exp(emit_t[h']) * sum_h exp(trans[h',h]) * p_t[h]
// with renormalization (scale by 1/p[0], track log offset) every 4 steps.
// ============================================================
__global__ void __launch_bounds__(64, 1)
crf_scan_kernel(const float* __restrict__ transition, const float* __restrict__ masks,
                const int* __restrict__ tags) {
    const int b = blockIdx.x;
    const int tid = threadIdx.x;
    const int h = tid;
    const int base = b * T_;

    __shared__ __align__(16) float pbuf[2][H_];
    __shared__ float red[64];

    // ---- gold score (all 64 threads over t) ----
    float partial = 0.0f, msum = 0.0f;
    for (int t = tid; t < T_; t += 64) {
        float mk = masks[base + t];
        int tg = tags[base + t];
        int pv = (t == 0) ? START_ : tags[base + t - 1];
        partial += mk * (g_emit[(size_t)(base + t) * H_ + tg] + transition[tg * H_ + pv]);
        msum += mk;
    }
    red[tid] = partial;
    __syncthreads();
    for (int s = 32; s > 0; s >>= 1) { if (tid < s) red[tid] += red[tid + s]; __syncthreads(); }
    float goldv = red[0];
    __syncthreads();
    red[tid] = msum;
    __syncthreads();
    for (int s = 32; s > 0; s >>= 1) { if (tid < s) red[tid] += red[tid + s]; __syncthreads(); }
    int last_pos = (int)(red[0] + 0.5f);
    __syncthreads();
    int last_tag = (last_pos > 0) ? tags[base + last_pos - 1] : START_;
    goldv += transition[STOP_ * H_ + last_tag];

    // ---- E row (exp of transition row h) packed as f32x2 pairs ----
    unsigned long long E2[26];
    if (h < H_) {
#pragma unroll
        for (int j = 0; j < 26; j++) {
            float a = __expf(transition[h * H_ + 2 * j]);
            float c = __expf(transition[h * H_ + 2 * j + 1]);
            E2[j] = pk2(a, c);
        }
    }

    // ---- init: p = onehot(START), offset = 0 ----
    if (h < H_) pbuf[0][h] = (h == START_) ? 1.0f : 0.0f;
    float pown = (h == START_) ? 1.0f : 0.0f;
    float offset = 0.0f;

    // prefetch emit (raw) + mask, pipeline depth 2; exp off critical path
    float emRaw1 = 0.0f, eEm = 0.0f;
    if (h < H_) {
        eEm   = __expf(g_emit[(size_t)base * H_ + h]);
        emRaw1 = g_emit[(size_t)(base + 1) * H_ + h];
    }
    float mk0 = masks[base + 0];
    float mk1 = masks[base + 1];
    __syncthreads();

    int cur = 0;
    for (int t = 0; t < T_; t++) {
        float rinv = 1.0f;
        if (((t & 3) == 0) && t) {
            float r = pbuf[cur][0];
            rinv = 1.0f / r;
            offset += __logf(r);
        }
        float pn = pown;
        if (h < H_) {
            const float4* pv = reinterpret_cast<const float4*>(&pbuf[cur][0]);
            unsigned long long a0 = 0ULL, a1 = 0ULL, a2 = 0ULL, a3 = 0ULL;
#pragma unroll
            for (int q = 0; q < 13; q++) {
                float4 p4 = pv[q];
                unsigned long long plo = pk2(p4.x, p4.y);
                unsigned long long phi = pk2(p4.z, p4.w);
                if (q & 1) { a2 = fma2(E2[2 * q], plo, a2); a3 = fma2(E2[2 * q + 1], phi, a3); }
                else       { a0 = fma2(E2[2 * q], plo, a0); a1 = fma2(E2[2 * q + 1], phi, a1); }
            }
            unsigned long long s01 = add2(a0, a1);
            unsigned long long s23 = add2(a2, a3);
            unsigned long long st  = add2(s01, s23);
            float lo, hi; upk2(st, lo, hi);
            float S = lo + hi;
            float upd = S * eEm;
            pn = (mk0 > 0.5f) ? upd : pown;
        }
        pn *= rinv;
        // rotate emit/mask pipeline
        float emNextRaw = emRaw1;
        mk0 = mk1;
        if (t + 2 < T_) {
            if (h < H_) emRaw1 = g_emit[(size_t)(base + t + 2) * H_ + h];
            mk1 = masks[base + t + 2];
        }
        eEm = __expf(emNextRaw);
        if (h < H_) pbuf[cur ^ 1][h] = pn;
        pown = pn;
        cur ^= 1;
        __syncthreads();
    }

    // ---- final: fwd = offset + log(sum_h p[h] * exp(trans[STOP,h])) ----
    float term = (h < H_) ? pown * __expf(transition[STOP_ * H_ + h]) : 0.0f;
    red[tid] = term;
    __syncthreads();
    for (int s = 32; s > 0; s >>= 1) { if (tid < s) red[tid] += red[tid + s]; __syncthreads(); }
    if (tid == 0) {
        float fwd = offset + __logf(red[0]);
        g_diff[b] = fwd - goldv;
    }
}

// ============================================================
// Kernel 3: mean over batches
// ============================================================
__global__ void __launch_bounds__(64)
finalize_kernel(float* __restrict__ out) {
    __shared__ float red[64];
    int tid = threadIdx.x;
    red[tid] = g_diff[tid];
    __syncthreads();
    for (int s = 32; s > 0; s >>= 1) { if (tid < s) red[tid] += red[tid + s]; __syncthreads(); }
    if (tid == 0) out[0] = red[0] * (1.0f / (float)B_);
}

// ============================================================
// launch
// inputs (metadata order): 0 features f32 [64,512,1024], 1 W f32 [52,1024],
// 2 b f32 [52], 3 transition f32 [52,52], 4 masks f32 [64,512], 5 tags i32 [64,512]
// ============================================================
extern "C" void kernel_launch(void* const* d_in, const int* in_sizes, int n_in,
                              void* d_out, int out_size) {
    const float* feat  = (const float*)d_in[0];
    const float* W     = (const float*)d_in[1];
    const float* bias  = (const float*)d_in[2];
    const float* trans = (const float*)d_in[3];
    const float* masks = (const float*)d_in[4];
    const int*   tags  = (const int*)d_in[5];
    float* out = (float*)d_out;

    emit_gemm_kernel<<<128, 256>>>(feat, W, bias);
    crf_scan_kernel<<<B_, 64>>>(trans, masks, tags);
    finalize_kernel<<<1, 64>>>(out);
}

// round 2
// speedup vs baseline: 1.3298x; 1.3298x over previous
#include <cuda_runtime.h>
#include <cuda_bf16.h>
#include <cstdint>

// Problem constants
#define B_    64
#define T_    512
#define F_    1024
#define H_    52
#define START_ 50
#define STOP_  51
#define BT_   (B_ * T_)

// Scratch (static device globals; no runtime allocation)
__device__ float g_emitT[(size_t)B_ * H_ * T_]; // emit transposed [b][h][t]
__device__ float g_diff[B_];                    // fwd - gold per batch

// ---------- packed fp32x2 helpers ----------
__device__ __forceinline__ unsigned long long pk2(float lo, float hi) {
    unsigned long long d;
    asm("mov.b64 %0, {%1, %2};" : "=l"(d) : "r"(__float_as_uint(lo)), "r"(__float_as_uint(hi)));
    return d;
}
__device__ __forceinline__ void upk2(unsigned long long v, float& lo, float& hi) {
    unsigned int a, b;
    asm("mov.b64 {%0, %1}, %2;" : "=r"(a), "=r"(b) : "l"(v));
    lo = __uint_as_float(a); hi = __uint_as_float(b);
}
__device__ __forceinline__ unsigned long long fma2(unsigned long long a, unsigned long long b,
                                                   unsigned long long c) {
    unsigned long long d;
    asm("fma.rn.f32x2 %0, %1, %2, %3;" : "=l"(d) : "l"(a), "l"(b), "l"(c));
    return d;
}
__device__ __forceinline__ unsigned long long add2(unsigned long long a, unsigned long long b) {
    unsigned long long d;
    asm("add.rn.f32x2 %0, %1, %2;" : "=l"(d) : "l"(a), "l"(b));
    return d;
}

// ============================================================
// Kernel 1: emit = features @ W^T + b   (M=32768, N=52, K=1024)
// 256 blocks x 256 threads, 2 CTAs/SM target. Block tile: 128 rows x 56 cols.
// Thread: 2 rows (rt, rt+64) x 7 col-pairs (f32x2).
// Output stored TRANSPOSED: g_emitT[b][h][t].
// ============================================================
__global__ void __launch_bounds__(256, 2)
emit_gemm_kernel(const float* __restrict__ feat, const float* __restrict__ W,
                 const float* __restrict__ bias) {
    __shared__ __align__(16) float sF[32 * 129];  // [kk][row], stride 129
    __shared__ __align__(16) float sW[32 * 68];   // [kk][colgroup*16 + c], c<14 valid

    const int tid = threadIdx.x;
    const int cg = tid >> 6;       // 0..3  (column group: 14 cols each)
    const int rt = tid & 63;       // 0..63 (row thread)
    const int blockRow = blockIdx.x * 128;

    const int lrow = tid >> 1;     // 0..127 (feature load row)
    const int ljj  = (tid & 1) * 4;// float4 index 0 or 4 within 8
    const int wkk  = tid & 31;
    const int whb  = tid >> 5;     // 0..7

    unsigned long long acc[2][7];
#pragma unroll
    for (int r = 0; r < 2; r++)
#pragma unroll
        for (int j = 0; j < 7; j++) acc[r][j] = 0ULL;

    float4 fv[4];
    float  wv[7];

    auto load_chunk = [&](int k0) {
#pragma unroll
        for (int it = 0; it < 4; it++) {
            fv[it] = *reinterpret_cast<const float4*>(
                &feat[(size_t)(blockRow + lrow) * F_ + k0 + (ljj + it) * 4]);
        }
#pragma unroll
        for (int it = 0; it < 7; it++) {
            int hh = whb + it * 8;  // 0..55
            wv[it] = (hh < H_) ? W[(size_t)hh * F_ + k0 + wkk] : 0.0f;
        }
    };
    auto store_chunk = [&]() {
#pragma unroll
        for (int it = 0; it < 4; it++) {
            int kkb = (ljj + it) * 4;
            sF[(kkb + 0) * 129 + lrow] = fv[it].x;
            sF[(kkb + 1) * 129 + lrow] = fv[it].y;
            sF[(kkb + 2) * 129 + lrow] = fv[it].z;
            sF[(kkb + 3) * 129 + lrow] = fv[it].w;
        }
#pragma unroll
        for (int it = 0; it < 7; it++) {
            int hh = whb + it * 8;
            int col = (hh / 14) * 16 + (hh % 14);
            sW[wkk * 68 + col] = wv[it];
        }
    };

    load_chunk(0);
    for (int k0 = 0; k0 < F_; k0 += 32) {
        __syncthreads();   // previous compute done
        store_chunk();
        __syncthreads();   // smem ready
        if (k0 + 32 < F_) load_chunk(k0 + 32);  // prefetch next (overlaps compute)

#pragma unroll 4
        for (int kk = 0; kk < 32; kk++) {
            float f0 = sF[kk * 129 + rt];
            float f1 = sF[kk * 129 + rt + 64];
            unsigned long long p0 = pk2(f0, f0);
            unsigned long long p1 = pk2(f1, f1);
            const float* wrow = &sW[kk * 68 + cg * 16];
            ulonglong2 wab = *reinterpret_cast<const ulonglong2*>(wrow);       // pairs 0,1
            ulonglong2 wcd = *reinterpret_cast<const ulonglong2*>(wrow + 4);   // pairs 2,3
            ulonglong2 wef = *reinterpret_cast<const ulonglong2*>(wrow + 8);   // pairs 4,5
            unsigned long long wg = *reinterpret_cast<const unsigned long long*>(wrow + 12); // pair 6
            acc[0][0] = fma2(p0, wab.x, acc[0][0]);
            acc[1][0] = fma2(p1, wab.x, acc[1][0]);
            acc[0][1] = fma2(p0, wab.y, acc[0][1]);
            acc[1][1] = fma2(p1, wab.y, acc[1][1]);
            acc[0][2] = fma2(p0, wcd.x, acc[0][2]);
            acc[1][2] = fma2(p1, wcd.x, acc[1][2]);
            acc[0][3] = fma2(p0, wcd.y, acc[0][3]);
            acc[1][3] = fma2(p1, wcd.y, acc[1][3]);
            acc[0][4] = fma2(p0, wef.x, acc[0][4]);
            acc[1][4] = fma2(p1, wef.x, acc[1][4]);
            acc[0][5] = fma2(p0, wef.y, acc[0][5]);
            acc[1][5] = fma2(p1, wef.y, acc[1][5]);
            acc[0][6] = fma2(p0, wg, acc[0][6]);
            acc[1][6] = fma2(p1, wg, acc[1][6]);
        }
    }

    // epilogue: + bias, store TRANSPOSED to g_emitT[b][h][t]
#pragma unroll
    for (int r = 0; r < 2; r++) {
        int row = blockRow + rt + r * 64;   // global (b*T + t)
        int b = row >> 9;                   // /512
        int t = row & 511;
        size_t bbase = (size_t)b * (H_ * T_);
#pragma unroll
        for (int j = 0; j < 7; j++) {
            int col = cg * 14 + 2 * j;
            if (col + 1 < H_) {
                float lo, hi;
                upk2(acc[r][j], lo, hi);
                lo += __ldg(&bias[col]);
                hi += __ldg(&bias[col + 1]);
                g_emitT[bbase + (size_t)col * T_ + t] = lo;
                g_emitT[bbase + (size_t)(col + 1) * T_ + t] = hi;
            }
        }
    }
}

// ============================================================
// Kernel 2: per-batch CRF forward (prob-space scan) + gold score
// 64 blocks x 64 threads. Thread h<52 owns destination state h.
// Emit streamed from transposed layout: one LDG.128 per 4 steps,
// pipelined 8+ steps deep so DRAM latency (577cyc) is hidden.
// ============================================================
__global__ void __launch_bounds__(64, 1)
crf_scan_kernel(const float* __restrict__ transition, const float* __restrict__ masks,
                const int* __restrict__ tags) {
    const int b = blockIdx.x;
    const int tid = threadIdx.x;
    const int h = tid;
    const int base = b * T_;
    const bool act = (h < H_);

    __shared__ __align__(16) float pbuf[2][H_];
    __shared__ float red[64];

    const float* embB = &g_emitT[(size_t)b * (H_ * T_)];
    const float* emh = &embB[(size_t)(act ? h : 0) * T_];

    // ---- gold score (all 64 threads over t) ----
    float partial = 0.0f, msum = 0.0f;
    for (int t = tid; t < T_; t += 64) {
        float mk = masks[base + t];
        int tg = tags[base + t];
        int pv = (t == 0) ? START_ : tags[base + t - 1];
        partial += mk * (embB[(size_t)tg * T_ + t] + transition[tg * H_ + pv]);
        msum += mk;
    }
    red[tid] = partial;
    __syncthreads();
    for (int s = 32; s > 0; s >>= 1) { if (tid < s) red[tid] += red[tid + s]; __syncthreads(); }
    float goldv = red[0];
    __syncthreads();
    red[tid] = msum;
    __syncthreads();
    for (int s = 32; s > 0; s >>= 1) { if (tid < s) red[tid] += red[tid + s]; __syncthreads(); }
    int last_pos = (int)(red[0] + 0.5f);
    __syncthreads();
    int last_tag = (last_pos > 0) ? tags[base + last_pos - 1] : START_;
    goldv += transition[STOP_ * H_ + last_tag];

    // ---- E row (exp of transition row h) packed as f32x2 pairs ----
    unsigned long long E2[26];
    if (act) {
#pragma unroll
        for (int j = 0; j < 26; j++) {
            float a = __expf(transition[h * H_ + 2 * j]);
            float c = __expf(transition[h * H_ + 2 * j + 1]);
            E2[j] = pk2(a, c);
        }
    }

    // ---- init: p = onehot(START), offset = 0 ----
    if (act) pbuf[0][h] = (h == START_) ? 1.0f : 0.0f;
    float pown = (h == START_) ? 1.0f : 0.0f;
    float offset = 0.0f;

    // ---- deep pipeline for emit + masks (4-step blocks, 8-12 step lookahead) ----
    const float4* m4p = reinterpret_cast<const float4*>(&masks[base]);
    float eCur[4];                // exps for current block (ready)
    float4 rawN, rawN2;           // raw emit for blocks tb+1, tb+2
    float4 mCur4, mN, mN2;
    if (act) {
        float4 r0 = *reinterpret_cast<const float4*>(emh);
        eCur[0] = __expf(r0.x); eCur[1] = __expf(r0.y);
        eCur[2] = __expf(r0.z); eCur[3] = __expf(r0.w);
        rawN  = *reinterpret_cast<const float4*>(emh + 4);
        rawN2 = *reinterpret_cast<const float4*>(emh + 8);
    }
    mCur4 = m4p[0]; mN = m4p[1]; mN2 = m4p[2];
    __syncthreads();

    int cur = 0;
    const int NB = T_ / 4;  // 128
    for (int tb = 0; tb < NB; tb++) {
        // issue the far-ahead loads first (deepest latency slack)
        float4 rawLd, mLd;
        bool haveLd = (tb + 3 < NB);
        if (haveLd) {
            if (act) rawLd = *reinterpret_cast<const float4*>(emh + (tb + 3) * 4);
            mLd = m4p[tb + 3];
        }
        // exps for NEXT block (MUFU off the critical path)
        float eNxt[4];
        eNxt[0] = __expf(rawN.x); eNxt[1] = __expf(rawN.y);
        eNxt[2] = __expf(rawN.z); eNxt[3] = __expf(rawN.w);

        float rinv = 1.0f;
        if (tb) {
            float r = pbuf[cur][0];
            rinv = 1.0f / r;
            offset += __logf(r);
        }
        float mk[4] = {mCur4.x, mCur4.y, mCur4.z, mCur4.w};

#pragma unroll
        for (int s = 0; s < 4; s++) {
            float pn = pown;
            if (act) {
                const float4* pv = reinterpret_cast<const float4*>(&pbuf[cur][0]);
                unsigned long long a0 = 0ULL, a1 = 0ULL, a2 = 0ULL, a3 = 0ULL;
#pragma unroll
                for (int q = 0; q < 13; q++) {
                    float4 p4 = pv[q];
                    unsigned long long plo = pk2(p4.x, p4.y);
                    unsigned long long phi = pk2(p4.z, p4.w);
                    if (q & 1) { a2 = fma2(E2[2 * q], plo, a2); a3 = fma2(E2[2 * q + 1], phi, a3); }
                    else       { a0 = fma2(E2[2 * q], plo, a0); a1 = fma2(E2[2 * q + 1], phi, a1); }
                }
                unsigned long long s01 = add2(a0, a1);
                unsigned long long s23 = add2(a2, a3);
                unsigned long long st  = add2(s01, s23);
                float lo, hi; upk2(st, lo, hi);
                float S = lo + hi;
                float upd = S * eCur[s];
                pn = (mk[s] > 0.5f) ? upd : pown;
            }
            if (s == 0) pn *= rinv;
            if (act) pbuf[cur ^ 1][h] = pn;
            pown = pn;
            cur ^= 1;
            __syncthreads();
        }

        // rotate pipelines
        eCur[0] = eNxt[0]; eCur[1] = eNxt[1]; eCur[2] = eNxt[2]; eCur[3] = eNxt[3];
        rawN = rawN2;
        mCur4 = mN; mN = mN2;
        if (haveLd) { rawN2 = rawLd; mN2 = mLd; }
    }

    // ---- final: fwd = offset + log(sum_h p[h] * exp(trans[STOP,h])) ----
    float term = act ? pown * __expf(transition[STOP_ * H_ + h]) : 0.0f;
    red[tid] = term;
    __syncthreads();
    for (int s = 32; s > 0; s >>= 1) { if (tid < s) red[tid] += red[tid + s]; __syncthreads(); }
    if (tid == 0) {
        float fwd = offset + __logf(red[0]);
        g_diff[b] = fwd - goldv;
    }
}

// ============================================================
// Kernel 3: mean over batches
// ============================================================
__global__ void __launch_bounds__(64)
finalize_kernel(float* __restrict__ out) {
    __shared__ float red[64];
    int tid = threadIdx.x;
    red[tid] = g_diff[tid];
    __syncthreads();
    for (int s = 32; s > 0; s >>= 1) { if (tid < s) red[tid] += red[tid + s]; __syncthreads(); }
    if (tid == 0) out[0] = red[0] * (1.0f / (float)B_);
}

// ============================================================
// launch
// ============================================================
extern "C" void kernel_launch(void* const* d_in, const int* in_sizes, int n_in,
                              void* d_out, int out_size) {
    const float* feat  = (const float*)d_in[0];
    const float* W     = (const float*)d_in[1];
    const float* bias  = (const float*)d_in[2];
    const float* trans = (const float*)d_in[3];
    const float* masks = (const float*)d_in[4];
    const int*   tags  = (const int*)d_in[5];
    float* out = (float*)d_out;

    emit_gemm_kernel<<<256, 256>>>(feat, W, bias);
    crf_scan_kernel<<<B_, 64>>>(trans, masks, tags);
    finalize_kernel<<<1, 64>>>(out);
}

// round 3
// speedup vs baseline: 1.3667x; 1.0277x over previous
#include <cuda_runtime.h>
#include <cuda_bf16.h>
#include <cstdint>

#define B_    64
#define T_    512
#define F_    1024
#define H_    52
#define START_ 50
#define STOP_  51
#define BT_   (B_ * T_)

__device__ float g_emitT[(size_t)B_ * H_ * T_]; // emit transposed [b][h][t]
__device__ float g_diff[B_];

// ---------- packed fp32x2 helpers ----------
__device__ __forceinline__ unsigned long long pk2(float lo, float hi) {
    unsigned long long d;
    asm("mov.b64 %0, {%1, %2};" : "=l"(d) : "r"(__float_as_uint(lo)), "r"(__float_as_uint(hi)));
    return d;
}
__device__ __forceinline__ void upk2(unsigned long long v, float& lo, float& hi) {
    unsigned int a, b;
    asm("mov.b64 {%0, %1}, %2;" : "=r"(a), "=r"(b) : "l"(v));
    lo = __uint_as_float(a); hi = __uint_as_float(b);
}
__device__ __forceinline__ unsigned long long fma2(unsigned long long a, unsigned long long b,
                                                   unsigned long long c) {
    unsigned long long d;
    asm("fma.rn.f32x2 %0, %1, %2, %3;" : "=l"(d) : "l"(a), "l"(b), "l"(c));
    return d;
}
__device__ __forceinline__ unsigned long long add2(unsigned long long a, unsigned long long b) {
    unsigned long long d;
    asm("add.rn.f32x2 %0, %1, %2;" : "=l"(d) : "l"(a), "l"(b));
    return d;
}

// ============================================================
// Kernel 1: emit = features @ W^T + b   (M=32768, N=52, K=1024)
// 128 blocks x 256 threads. Block tile: 256 rows x 56 cols.
// Thread: 4 rows x 7 col-pairs (f32x2). Double-buffered smem,
// one __syncthreads per 32-k chunk; sF stored pre-splatted (f,f).
// Output stored TRANSPOSED: g_emitT[b][h][t].
// ============================================================
#define SF_STRIDE 514              // floats per kk row (256 rows duplicated + pad)
#define SW_STRIDE 72
#define SF_BUF    (32 * SF_STRIDE) // floats per buffer
#define SW_BUF    (32 * SW_STRIDE)
#define GEMM_SMEM_BYTES ((2 * SF_BUF + 2 * SW_BUF) * 4)

__global__ void __launch_bounds__(256, 1)
emit_gemm_kernel(const float* __restrict__ feat, const float* __restrict__ W,
                 const float* __restrict__ bias) {
    extern __shared__ __align__(16) float smem[];
    float* sF = smem;                   // 2 buffers of [32][514]
    float* sW = smem + 2 * SF_BUF;      // 2 buffers of [32][72]

    const int tid = threadIdx.x;
    const int cg = tid >> 6;       // 0..3  (14 cols each)
    const int rt = tid & 63;       // 0..63
    const int blockRow = blockIdx.x * 256;

    const int lrow = tid >> 3;     // 0..31
    const int ljj  = tid & 7;      // 0..7
    const int wkk  = tid & 31;
    const int whb  = tid >> 5;     // 0..7

    unsigned long long acc[4][7];
#pragma unroll
    for (int r = 0; r < 4; r++)
#pragma unroll
        for (int j = 0; j < 7; j++) acc[r][j] = 0ULL;

    float4 fv[8];
    float  wv[7];

    auto load_chunk = [&](int k0) {
#pragma unroll
        for (int it = 0; it < 8; it++) {
            int row = lrow + it * 32;
            fv[it] = *reinterpret_cast<const float4*>(
                &feat[(size_t)(blockRow + row) * F_ + k0 + ljj * 4]);
        }
#pragma unroll
        for (int it = 0; it < 7; it++) {
            int hh = whb + it * 8;  // 0..55
            wv[it] = (hh < H_) ? W[(size_t)hh * F_ + k0 + wkk] : 0.0f;
        }
    };
    auto store_chunk = [&](int buf) {
        float* f = sF + buf * SF_BUF;
        float* w = sW + buf * SW_BUF;
#pragma unroll
        for (int it = 0; it < 8; it++) {
            int row2 = (lrow + it * 32) * 2;
            int kkb = ljj * 4;
            *reinterpret_cast<unsigned long long*>(&f[(kkb + 0) * SF_STRIDE + row2]) = pk2(fv[it].x, fv[it].x);
            *reinterpret_cast<unsigned long long*>(&f[(kkb + 1) * SF_STRIDE + row2]) = pk2(fv[it].y, fv[it].y);
            *reinterpret_cast<unsigned long long*>(&f[(kkb + 2) * SF_STRIDE + row2]) = pk2(fv[it].z, fv[it].z);
            *reinterpret_cast<unsigned long long*>(&f[(kkb + 3) * SF_STRIDE + row2]) = pk2(fv[it].w, fv[it].w);
        }
#pragma unroll
        for (int it = 0; it < 7; it++) {
            int hh = whb + it * 8;
            int col = (hh / 14) * 16 + (hh % 14);
            w[wkk * SW_STRIDE + col] = wv[it];
        }
    };
    auto compute = [&](int buf) {
        const float* fbase = sF + buf * SF_BUF;
        const float* wbase = sW + buf * SW_BUF;
#pragma unroll 4
        for (int kk = 0; kk < 32; kk++) {
            const float* fb = fbase + kk * SF_STRIDE;
            unsigned long long p0 = *reinterpret_cast<const unsigned long long*>(&fb[2 * rt]);
            unsigned long long p1 = *reinterpret_cast<const unsigned long long*>(&fb[2 * (rt + 64)]);
            unsigned long long p2 = *reinterpret_cast<const unsigned long long*>(&fb[2 * (rt + 128)]);
            unsigned long long p3 = *reinterpret_cast<const unsigned long long*>(&fb[2 * (rt + 192)]);
            const float* wrow = wbase + kk * SW_STRIDE + cg * 16;
            ulonglong2 wab = *reinterpret_cast<const ulonglong2*>(wrow);
            ulonglong2 wcd = *reinterpret_cast<const ulonglong2*>(wrow + 4);
            ulonglong2 wef = *reinterpret_cast<const ulonglong2*>(wrow + 8);
            unsigned long long wg = *reinterpret_cast<const unsigned long long*>(wrow + 12);
            acc[0][0] = fma2(p0, wab.x, acc[0][0]);
            acc[1][0] = fma2(p1, wab.x, acc[1][0]);
            acc[2][0] = fma2(p2, wab.x, acc[2][0]);
            acc[3][0] = fma2(p3, wab.x, acc[3][0]);
            acc[0][1] = fma2(p0, wab.y, acc[0][1]);
            acc[1][1] = fma2(p1, wab.y, acc[1][1]);
            acc[2][1] = fma2(p2, wab.y, acc[2][1]);
            acc[3][1] = fma2(p3, wab.y, acc[3][1]);
            acc[0][2] = fma2(p0, wcd.x, acc[0][2]);
            acc[1][2] = fma2(p1, wcd.x, acc[1][2]);
            acc[2][2] = fma2(p2, wcd.x, acc[2][2]);
            acc[3][2] = fma2(p3, wcd.x, acc[3][2]);
            acc[0][3] = fma2(p0, wcd.y, acc[0][3]);
            acc[1][3] = fma2(p1, wcd.y, acc[1][3]);
            acc[2][3] = fma2(p2, wcd.y, acc[2][3]);
            acc[3][3] = fma2(p3, wcd.y, acc[3][3]);
            acc[0][4] = fma2(p0, wef.x, acc[0][4]);
            acc[1][4] = fma2(p1, wef.x, acc[1][4]);
            acc[2][4] = fma2(p2, wef.x, acc[2][4]);
            acc[3][4] = fma2(p3, wef.x, acc[3][4]);
            acc[0][5] = fma2(p0, wef.y, acc[0][5]);
            acc[1][5] = fma2(p1, wef.y, acc[1][5]);
            acc[2][5] = fma2(p2, wef.y, acc[2][5]);
            acc[3][5] = fma2(p3, wef.y, acc[3][5]);
            acc[0][6] = fma2(p0, wg, acc[0][6]);
            acc[1][6] = fma2(p1, wg, acc[1][6]);
            acc[2][6] = fma2(p2, wg, acc[2][6]);
            acc[3][6] = fma2(p3, wg, acc[3][6]);
        }
    };

    // prologue: fill buf0 (chunk0), fetch chunk1 into regs
    load_chunk(0);
    store_chunk(0);
    load_chunk(32);
    __syncthreads();

#pragma unroll 1
    for (int c = 0; c < 32; c++) {
        if (c + 1 < 32) store_chunk((c + 1) & 1);   // regs hold chunk c+1
        if (c + 2 < 32) load_chunk((c + 2) * 32);   // prefetch 2 ahead
        compute(c & 1);
        __syncthreads();
    }

    // epilogue: + bias, store TRANSPOSED to g_emitT[b][h][t]
#pragma unroll
    for (int r = 0; r < 4; r++) {
        int row = blockRow + rt + r * 64;   // global (b*T + t)
        int b = row >> 9;
        int t = row & 511;
        size_t bbase = (size_t)b * (H_ * T_);
#pragma unroll
        for (int j = 0; j < 7; j++) {
            int col = cg * 14 + 2 * j;
            if (col + 1 < H_) {
                float lo, hi;
                upk2(acc[r][j], lo, hi);
                lo += __ldg(&bias[col]);
                hi += __ldg(&bias[col + 1]);
                g_emitT[bbase + (size_t)col * T_ + t] = lo;
                g_emitT[bbase + (size_t)(col + 1) * T_ + t] = hi;
            }
        }
    }
}

// ============================================================
// Kernel 2: per-batch CRF forward — SINGLE WARP per batch.
// Lane owns states (lane, lane+32). p exchanged via smem with
// __syncwarp only (no block barrier). Prob-space recurrence with
// renorm every 4 steps (scalar via shfl from lane 0).
// ============================================================
__global__ void __launch_bounds__(32, 1)
crf_scan_kernel(const float* __restrict__ transition, const float* __restrict__ masks,
                const int* __restrict__ tags) {
    const int b = blockIdx.x;
    const int lane = threadIdx.x;
    const int h0 = lane;
    const int h1 = lane + 32;
    const bool act1 = (h1 < H_);   // lane < 20
    const int base = b * T_;
    const unsigned FULL = 0xFFFFFFFFu;

    __shared__ __align__(16) float pbuf[2][52];

    const float* embB = &g_emitT[(size_t)b * (H_ * T_)];

    // ---- gold score ----
    float partial = 0.0f, msum = 0.0f;
    for (int t = lane; t < T_; t += 32) {
        float mk = masks[base + t];
        int tg = tags[base + t];
        int pv = (t == 0) ? START_ : tags[base + t - 1];
        partial += mk * (embB[(size_t)tg * T_ + t] + transition[tg * H_ + pv]);
        msum += mk;
    }
#pragma unroll
    for (int s = 16; s > 0; s >>= 1) {
        partial += __shfl_xor_sync(FULL, partial, s);
        msum    += __shfl_xor_sync(FULL, msum, s);
    }
    float goldv = partial;
    int last_pos = (int)(msum + 0.5f);
    int last_tag = (last_pos > 0) ? tags[base + last_pos - 1] : START_;
    goldv += transition[STOP_ * H_ + last_tag];

    // ---- E rows (exp of transition rows h0, h1), packed f32x2 ----
    unsigned long long E0[26], E1[26];
    {
        const float* r0 = &transition[h0 * H_];
        const float* r1 = &transition[(act1 ? h1 : 0) * H_];
#pragma unroll
        for (int j = 0; j < 26; j++) {
            E0[j] = pk2(__expf(r0[2 * j]), __expf(r0[2 * j + 1]));
            E1[j] = pk2(__expf(r1[2 * j]), __expf(r1[2 * j + 1]));
        }
    }

    // ---- init ----
    pbuf[0][h0] = (h0 == START_) ? 1.0f : 0.0f;
    if (act1) pbuf[0][h1] = (h1 == START_) ? 1.0f : 0.0f;
    float pown0 = (h0 == START_) ? 1.0f : 0.0f;
    float pown1 = (h1 == START_) ? 1.0f : 0.0f;
    float offset = 0.0f;

    // ---- emit/mask deep pipeline (4-step blocks, 12-step lookahead) ----
    const float* emh0 = &embB[(size_t)h0 * T_];
    const float* emh1 = &embB[(size_t)(act1 ? h1 : 0) * T_];
    const float4* m4p = reinterpret_cast<const float4*>(&masks[base]);

    float eCur0[4], eCur1[4];
    float4 rawN0, rawN20, rawN1, rawN21, mCur4, mN, mN2;
    {
        float4 r0 = *reinterpret_cast<const float4*>(emh0);
        float4 r1 = *reinterpret_cast<const float4*>(emh1);
        eCur0[0] = __expf(r0.x); eCur0[1] = __expf(r0.y); eCur0[2] = __expf(r0.z); eCur0[3] = __expf(r0.w);
        eCur1[0] = __expf(r1.x); eCur1[1] = __expf(r1.y); eCur1[2] = __expf(r1.z); eCur1[3] = __expf(r1.w);
        rawN0  = *reinterpret_cast<const float4*>(emh0 + 4);
        rawN1  = *reinterpret_cast<const float4*>(emh1 + 4);
        rawN20 = *reinterpret_cast<const float4*>(emh0 + 8);
        rawN21 = *reinterpret_cast<const float4*>(emh1 + 8);
    }
    mCur4 = m4p[0]; mN = m4p[1]; mN2 = m4p[2];
    __syncwarp();

    int cur = 0;
    const int NB = T_ / 4;  // 128
    for (int tb = 0; tb < NB; tb++) {
        float4 rawLd0, rawLd1, mLd;
        bool haveLd = (tb + 3 < NB);
        if (haveLd) {
            rawLd0 = *reinterpret_cast<const float4*>(emh0 + (tb + 3) * 4);
            rawLd1 = *reinterpret_cast<const float4*>(emh1 + (tb + 3) * 4);
            mLd = m4p[tb + 3];
        }
        float eN0[4], eN1[4];
        eN0[0] = __expf(rawN0.x); eN0[1] = __expf(rawN0.y); eN0[2] = __expf(rawN0.z); eN0[3] = __expf(rawN0.w);
        eN1[0] = __expf(rawN1.x); eN1[1] = __expf(rawN1.y); eN1[2] = __expf(rawN1.z); eN1[3] = __expf(rawN1.w);

        float rinv = 1.0f;
        if (tb) {
            float r = __shfl_sync(FULL, pown0, 0);   // p[state 0]
            rinv = 1.0f / r;
            offset += __logf(r);
        }
        float mk[4] = {mCur4.x, mCur4.y, mCur4.z, mCur4.w};

#pragma unroll
        for (int s = 0; s < 4; s++) {
            const float4* pv = reinterpret_cast<const float4*>(&pbuf[cur][0]);
            unsigned long long a0 = 0ULL, a1 = 0ULL, a2 = 0ULL, a3 = 0ULL;
            unsigned long long c0 = 0ULL, c1 = 0ULL, c2 = 0ULL, c3 = 0ULL;
#pragma unroll
            for (int q = 0; q < 13; q++) {
                float4 p4 = pv[q];
                unsigned long long plo = pk2(p4.x, p4.y);
                unsigned long long phi = pk2(p4.z, p4.w);
                if (q & 1) {
                    a2 = fma2(E0[2 * q], plo, a2); a3 = fma2(E0[2 * q + 1], phi, a3);
                    c2 = fma2(E1[2 * q], plo, c2); c3 = fma2(E1[2 * q + 1], phi, c3);
                } else {
                    a0 = fma2(E0[2 * q], plo, a0); a1 = fma2(E0[2 * q + 1], phi, a1);
                    c0 = fma2(E1[2 * q], plo, c0); c1 = fma2(E1[2 * q + 1], phi, c1);
                }
            }
            unsigned long long sa = add2(add2(a0, a1), add2(a2, a3));
            unsigned long long sc = add2(add2(c0, c1), add2(c2, c3));
            float la, ha, lc, hc;
            upk2(sa, la, ha);
            upk2(sc, lc, hc);
            float S0 = la + ha;
            float S1 = lc + hc;
            bool on = (mk[s] > 0.5f);
            float pn0 = on ? S0 * eCur0[s] : pown0;
            float pn1 = on ? S1 * eCur1[s] : pown1;
            if (s == 0) { pn0 *= rinv; pn1 *= rinv; }
            pbuf[cur ^ 1][h0] = pn0;
            if (act1) pbuf[cur ^ 1][h1] = pn1;
            pown0 = pn0; pown1 = pn1;
            cur ^= 1;
            __syncwarp();
        }

        eCur0[0] = eN0[0]; eCur0[1] = eN0[1]; eCur0[2] = eN0[2]; eCur0[3] = eN0[3];
        eCur1[0] = eN1[0]; eCur1[1] = eN1[1]; eCur1[2] = eN1[2]; eCur1[3] = eN1[3];
        rawN0 = rawN20; rawN1 = rawN21;
        mCur4 = mN; mN = mN2;
        if (haveLd) { rawN20 = rawLd0; rawN21 = rawLd1; mN2 = mLd; }
    }

    // ---- final: fwd = offset + log(sum_h p[h] * exp(trans[STOP,h])) ----
    float term = pown0 * __expf(transition[STOP_ * H_ + h0]);
    if (act1) term += pown1 * __expf(transition[STOP_ * H_ + h1]);
#pragma unroll
    for (int s = 16; s > 0; s >>= 1) term += __shfl_xor_sync(FULL, term, s);
    if (lane == 0) {
        float fwd = offset + __logf(term);
        g_diff[b] = fwd - goldv;
    }
}

// ============================================================
// Kernel 3: mean over batches
// ============================================================
__global__ void __launch_bounds__(64)
finalize_kernel(float* __restrict__ out) {
    __shared__ float red[64];
    int tid = threadIdx.x;
    red[tid] = g_diff[tid];
    __syncthreads();
    for (int s = 32; s > 0; s >>= 1) { if (tid < s) red[tid] += red[tid + s]; __syncthreads(); }
    if (tid == 0) out[0] = red[0] * (1.0f / (float)B_);
}

// ============================================================
// launch
// ============================================================
extern "C" void kernel_launch(void* const* d_in, const int* in_sizes, int n_in,
                              void* d_out, int out_size) {
    const float* feat  = (const float*)d_in[0];
    const float* W     = (const float*)d_in[1];
    const float* bias  = (const float*)d_in[2];
    const float* trans = (const float*)d_in[3];
    const float* masks = (const float*)d_in[4];
    const int*   tags  = (const int*)d_in[5];
    float* out = (float*)d_out;

    cudaFuncSetAttribute(emit_gemm_kernel,
                         cudaFuncAttributeMaxDynamicSharedMemorySize, GEMM_SMEM_BYTES);

    emit_gemm_kernel<<<128, 256, GEMM_SMEM_BYTES>>>(feat, W, bias);
    crf_scan_kernel<<<B_, 32>>>(trans, masks, tags);
    finalize_kernel<<<1, 64>>>(out);
}